// round 7
// baseline (speedup 1.0000x reference)
#include <cuda_runtime.h>
#include <cstdint>
#include <cmath>

#define B_SZ   64
#define KCP    16
#define NDIM   19            // K + 3
#define NSLOT  20            // coeff slots: 0=const,1=x,2=y,3..18=RBF k0..15,19=pad
#define HH     512
#define WW     512
#define HWPIX  (HH * WW)
#define PAIRS  (HWPIX / 2)   // 131072 pixel pairs, 1 per thread

// inv_delta[:, :16] passed by value (computed on host — input-independent).
struct InvW {
    float w[NDIM][KCP];
};

// ---------------------------------------------------------------------------
// Packed f32x2 helpers (sm_103a).
// ---------------------------------------------------------------------------
__device__ __forceinline__ unsigned long long pack2(float lo, float hi) {
    unsigned long long r;
    asm("mov.b64 %0, {%1, %2};" : "=l"(r) : "f"(lo), "f"(hi));
    return r;
}
__device__ __forceinline__ unsigned long long fma2(unsigned long long a,
                                                   unsigned long long b,
                                                   unsigned long long c) {
    unsigned long long d;
    asm("fma.rn.f32x2 %0, %1, %2, %3;" : "=l"(d) : "l"(a), "l"(b), "l"(c));
    return d;
}
__device__ __forceinline__ unsigned long long add2(unsigned long long a,
                                                   unsigned long long b) {
    unsigned long long d;
    asm("add.rn.f32x2 %0, %1, %2;" : "=l"(d) : "l"(a), "l"(b));
    return d;
}
__device__ __forceinline__ float2 unpk(unsigned long long a) {
    float2 f;
    asm("mov.b64 {%0, %1}, %2;" : "=f"(f.x), "=f"(f.y) : "l"(a));
    return f;
}

// ---------------------------------------------------------------------------
// Fused kernel. Lanes = the 2 pixels of the pair.
//   basis  u[k] = (v_px0[k], v_px1[k])   — built packed, no dup movs
//   coeffs duplicated in SMEM: (c,c) per dim — dup done once per block
//   output unpack is register aliasing (free), no cross-lane math.
// ---------------------------------------------------------------------------
__global__ void __launch_bounds__(256, 4) tps_fused_kernel(
    InvW inv, const float* __restrict__ sp, float4* __restrict__ out) {

    __shared__ __align__(16) float2 s_cx[B_SZ][NSLOT];  // 10 KB  (c.x, c.x)
    __shared__ __align__(16) float2 s_cy[B_SZ][NSLOT];  // 10 KB  (c.y, c.y)
    __shared__ float s_sp[B_SZ * KCP * 2];              // 8 KB

    const int tid = threadIdx.x;

    // Stage source points (2048 floats).
    {
        const float4* sp4 = reinterpret_cast<const float4*>(sp);
        float4* dst = reinterpret_cast<float4*>(s_sp);
        #pragma unroll
        for (int i = 0; i < 2; i++) dst[tid + 256 * i] = sp4[tid + 256 * i];
    }
    __syncthreads();

    // coeff[b][i][d] = sum_{j<16} invW[i][j] * sp[b][j][d]; store lane-duplicated.
    for (int t = tid; t < B_SZ * NDIM; t += 256) {
        const int b = t / NDIM, i = t - b * NDIM;
        const float* spb = s_sp + b * (KCP * 2);
        float ax = 0.0f, ay = 0.0f;
        #pragma unroll
        for (int j = 0; j < KCP; j++) {
            const float w = inv.w[i][j];
            ax = fmaf(w, spb[2 * j + 0], ax);
            ay = fmaf(w, spb[2 * j + 1], ay);
        }
        const int slot = (i < KCP) ? (3 + i) : (i - KCP);  // affine first
        s_cx[b][slot] = make_float2(ax, ax);
        s_cy[b][slot] = make_float2(ay, ay);
    }
    for (int b = tid; b < B_SZ; b += 256) {
        s_cx[b][19] = make_float2(0.0f, 0.0f);
        s_cy[b][19] = make_float2(0.0f, 0.0f);
    }
    __syncthreads();

    // ---- per-thread pixel pair ----
    const int t  = blockIdx.x * 256 + tid;
    const int n0 = t * 2;
    const int w0 = n0 & (WW - 1);
    const int h  = n0 >> 9;
    const float X0 = fmaf((float)w0, 2.0f / (float)(WW - 1), -1.0f);
    const float X1 = X0 + 2.0f / (float)(WW - 1);
    const float Y  = fmaf((float)h, 2.0f / (float)(HH - 1), -1.0f);

    const unsigned long long Xp = pack2(X0, X1);

    // up[0] = Y-term (slot 2); up[1..16] = RBF k0..15 (slots 3..18).
    unsigned long long up[17];
    up[0] = pack2(Y, Y);
    #pragma unroll
    for (int k = 0; k < KCP; k++) {
        const float cx = -1.0f + (float)(k >> 2) * (2.0f / 3.0f);
        const float cy = -1.0f + (float)(k & 3) * (2.0f / 3.0f);
        const float dy  = Y - cy;
        const float dy2 = dy * dy;
        float dxa = X0 - cx;
        float r2a = fmaf(dxa, dxa, dy2);
        float va  = r2a * __logf(r2a + 1e-6f);
        float dxb = X1 - cx;
        float r2b = fmaf(dxb, dxb, dy2);
        float vb  = r2b * __logf(r2b + 1e-6f);
        up[1 + k] = pack2(va, vb);
    }

    for (int b = 0; b < B_SZ; b++) {
        const ulonglong2* cxp = reinterpret_cast<const ulonglong2*>(s_cx[b]);
        const ulonglong2* cyp = reinterpret_cast<const ulonglong2*>(s_cy[b]);
        const unsigned long long* cxs = reinterpret_cast<const unsigned long long*>(s_cx[b]);
        const unsigned long long* cys = reinterpret_cast<const unsigned long long*>(s_cy[b]);

        // slots 0,1: const + X
        const ulonglong2 qx0 = cxp[0];
        const ulonglong2 qy0 = cyp[0];
        unsigned long long ax0 = fma2(Xp, qx0.y, qx0.x);
        unsigned long long ay0 = fma2(Xp, qy0.y, qy0.x);
        unsigned long long ax1 = 0ULL, ay1 = 0ULL;

        // slots 2..17 in pairs (m = 1..8)
        #pragma unroll
        for (int m = 1; m < 9; m++) {
            const ulonglong2 qx = cxp[m];
            const ulonglong2 qy = cyp[m];
            ax0 = fma2(up[2 * m - 2], qx.x, ax0);
            ax1 = fma2(up[2 * m - 1], qx.y, ax1);
            ay0 = fma2(up[2 * m - 2], qy.x, ay0);
            ay1 = fma2(up[2 * m - 1], qy.y, ay1);
        }
        // slot 18 (RBF k15), LDS.64
        ax0 = fma2(up[16], cxs[18], ax0);
        ay0 = fma2(up[16], cys[18], ay0);

        const float2 fx = unpk(add2(ax0, ax1));   // (x@px0, x@px1)
        const float2 fy = unpk(add2(ay0, ay1));   // (y@px0, y@px1)
        out[(size_t)b * PAIRS + t] = make_float4(fx.x, fy.x, fx.y, fy.y);
    }
}

// ---------------------------------------------------------------------------
// Host: build delta(19x19), invert (Gauss-Jordan, partial pivoting, fp64).
// Input-independent -> runs on CPU at capture time; rides in as kernel param.
// ---------------------------------------------------------------------------
static inline double h_cpx(int k) { return -1.0 + (double)(k >> 2) * (2.0 / 3.0); }
static inline double h_cpy(int k) { return -1.0 + (double)(k & 3) * (2.0 / 3.0); }

static void build_invw(InvW* out) {
    double M[NDIM][2 * NDIM];
    for (int r = 0; r < NDIM; r++)
        for (int c = 0; c < 2 * NDIM; c++) {
            double v = 0.0;
            if (c >= NDIM) {
                v = (c - NDIM == r) ? 1.0 : 0.0;
            } else if (r < KCP && c < KCP) {
                double dx = h_cpx(r) - h_cpx(c);
                double dy = h_cpy(r) - h_cpy(c);
                double r2 = dx * dx + dy * dy;
                v = r2 * log(r2 + 1e-6);
            } else if (r < KCP) {
                v = (c == KCP) ? 1.0 : ((c == KCP + 1) ? h_cpx(r) : h_cpy(r));
            } else if (c < KCP) {
                v = (r == KCP) ? 1.0 : ((r == KCP + 1) ? h_cpx(c) : h_cpy(c));
            }
            M[r][c] = v;
        }

    for (int p = 0; p < NDIM; p++) {
        int best = p;
        double bm = fabs(M[p][p]);
        for (int r = p + 1; r < NDIM; r++) {
            double m = fabs(M[r][p]);
            if (m > bm) { bm = m; best = r; }
        }
        if (best != p)
            for (int c = 0; c < 2 * NDIM; c++) {
                double tv = M[p][c]; M[p][c] = M[best][c]; M[best][c] = tv;
            }
        const double inv = 1.0 / M[p][p];
        for (int c = 0; c < 2 * NDIM; c++) M[p][c] *= inv;
        for (int r = 0; r < NDIM; r++) {
            if (r == p) continue;
            const double f = M[r][p];
            if (f == 0.0) continue;
            for (int c = 0; c < 2 * NDIM; c++) M[r][c] -= f * M[p][c];
        }
    }

    for (int i = 0; i < NDIM; i++)
        for (int j = 0; j < KCP; j++)
            out->w[i][j] = (float)M[i][NDIM + j];
}

// ---------------------------------------------------------------------------
extern "C" void kernel_launch(void* const* d_in, const int* in_sizes, int n_in,
                              void* d_out, int out_size) {
    const float* sp = (const float*)d_in[0];        // [64, 16, 2] fp32
    float4* out = (float4*)d_out;                   // [64, 512, 512, 2] fp32

    InvW inv;
    build_invw(&inv);                               // host-side, capture-time only

    tps_fused_kernel<<<PAIRS / 256, 256>>>(inv, sp, out);
}

// round 9
// speedup vs baseline: 1.3568x; 1.3568x over previous
#include <cuda_runtime.h>
#include <cstdint>
#include <cmath>

#define B_SZ   64
#define KCP    16
#define NDIM   19            // K + 3
#define NPAD   20            // padded coeff rows per batch (16B alignment)
#define HH     512
#define WW     512
#define HWPIX  (HH * WW)
#define PAIRS  (HWPIX / 2)   // 131072 pixel pairs, 1 per thread

// inv_delta[:, :16] passed by value (computed on host — input-independent).
struct InvW {
    float w[NDIM][KCP];
};

// ---------------------------------------------------------------------------
// Packed f32x2 helpers (sm_103a).
// ---------------------------------------------------------------------------
__device__ __forceinline__ unsigned long long pack2(float lo, float hi) {
    unsigned long long r;
    asm("mov.b64 %0, {%1, %2};" : "=l"(r) : "f"(lo), "f"(hi));
    return r;
}
__device__ __forceinline__ unsigned long long fma2(unsigned long long a,
                                                   unsigned long long b,
                                                   unsigned long long c) {
    unsigned long long d;
    asm("fma.rn.f32x2 %0, %1, %2, %3;" : "=l"(d) : "l"(a), "l"(b), "l"(c));
    return d;
}
__device__ __forceinline__ unsigned long long add2(unsigned long long a,
                                                   unsigned long long b) {
    unsigned long long d;
    asm("add.rn.f32x2 %0, %1, %2;" : "=l"(d) : "l"(a), "l"(b));
    return d;
}

// ---------------------------------------------------------------------------
// Fused kernel = R5's main loop + in-block coeff prologue.
//   lanes = output dims (x, y); coeff row i stored as float2 (cx_i, cy_i);
//   one LDS.128 (ulonglong2) feeds BOTH dims of TWO rows -> 10 LDS/batch.
//   Basis u2[k] = (v_k, v_k) duplicated: 40 regs, shared across both pixels'
//   accumulator chains only via separate u-arrays per pixel (as in R5).
// ---------------------------------------------------------------------------
__global__ void __launch_bounds__(256, 4) tps_fused_kernel(
    InvW inv, const float* __restrict__ sp, ulonglong2* __restrict__ out) {

    __shared__ __align__(16) float2 s_coeff[B_SZ * NPAD];  // 10 KB
    __shared__ float s_sp[B_SZ * KCP * 2];                 // 8 KB

    const int tid = threadIdx.x;

    // Stage source points (2048 floats = 512 float4).
    {
        const float4* sp4 = reinterpret_cast<const float4*>(sp);
        float4* dst = reinterpret_cast<float4*>(s_sp);
        dst[tid]       = sp4[tid];
        dst[tid + 256] = sp4[tid + 256];
    }
    __syncthreads();

    // coeff[b][i][d] = sum_{j<16} invW[i][j] * sp[b][j][d]  (redundant per block)
    for (int t = tid; t < B_SZ * NDIM; t += 256) {
        const int b = t / NDIM, i = t - b * NDIM;
        const float* spb = s_sp + b * (KCP * 2);
        float ax = 0.0f, ay = 0.0f;
        #pragma unroll
        for (int j = 0; j < KCP; j++) {
            const float w = inv.w[i][j];
            ax = fmaf(w, spb[2 * j + 0], ax);
            ay = fmaf(w, spb[2 * j + 1], ay);
        }
        s_coeff[b * NPAD + i] = make_float2(ax, ay);
    }
    for (int b = tid; b < B_SZ; b += 256) {
        s_coeff[b * NPAD + NDIM] = make_float2(0.0f, 0.0f);
    }
    __syncthreads();

    // ---- per-thread pixel pair (R5 main loop) ----
    const int t  = blockIdx.x * 256 + tid;
    const int n0 = t * 2;
    const int w0 = n0 & (WW - 1);
    const int h  = n0 >> 9;
    const float X0 = fmaf((float)w0, 2.0f / (float)(WW - 1), -1.0f);
    const float X1 = X0 + 2.0f / (float)(WW - 1);
    const float Y  = fmaf((float)h, 2.0f / (float)(HH - 1), -1.0f);

    unsigned long long u0[KCP], u1[KCP];
    #pragma unroll
    for (int k = 0; k < KCP; k++) {
        const float cx = -1.0f + (float)(k >> 2) * (2.0f / 3.0f);
        const float cy = -1.0f + (float)(k & 3) * (2.0f / 3.0f);
        const float dy  = Y - cy;
        const float dy2 = dy * dy;
        {
            float dx = X0 - cx;
            float r2 = fmaf(dx, dx, dy2);
            float u  = r2 * __logf(r2 + 1e-6f);
            u0[k] = pack2(u, u);
        }
        {
            float dx = X1 - cx;
            float r2 = fmaf(dx, dx, dy2);
            float u  = r2 * __logf(r2 + 1e-6f);
            u1[k] = pack2(u, u);
        }
    }
    const unsigned long long X0d = pack2(X0, X0);
    const unsigned long long X1d = pack2(X1, X1);
    const unsigned long long Yd  = pack2(Y, Y);

    #pragma unroll 4
    for (int b = 0; b < B_SZ; b++) {
        const ulonglong2* cc = reinterpret_cast<const ulonglong2*>(s_coeff + b * NPAD);
        // Affine part: rows 16 (const), 17 (x), 18 (y)
        const ulonglong2 c8 = cc[8];   // rows 16, 17
        const ulonglong2 c9 = cc[9];   // rows 18, pad
        unsigned long long a0 = fma2(X0d, c8.y, c8.x);
        unsigned long long a1 = fma2(X1d, c8.y, c8.x);
        a0 = fma2(Yd, c9.x, a0);
        a1 = fma2(Yd, c9.x, a1);
        unsigned long long b0 = 0ULL, b1 = 0ULL;
        #pragma unroll
        for (int j = 0; j < 8; j++) {
            const ulonglong2 c = cc[j];           // rows 2j, 2j+1 (broadcast LDS.128)
            a0 = fma2(u0[2 * j + 0], c.x, a0);
            b0 = fma2(u0[2 * j + 1], c.y, b0);
            a1 = fma2(u1[2 * j + 0], c.x, a1);
            b1 = fma2(u1[2 * j + 1], c.y, b1);
        }
        ulonglong2 r;
        r.x = add2(a0, b0);
        r.y = add2(a1, b1);
        out[(size_t)b * PAIRS + t] = r;           // STG.128
    }
}

// ---------------------------------------------------------------------------
// Host: build delta(19x19), invert (Gauss-Jordan, partial pivoting, fp64).
// Input-independent -> runs on CPU at capture time; rides in as kernel param.
// ---------------------------------------------------------------------------
static inline double h_cpx(int k) { return -1.0 + (double)(k >> 2) * (2.0 / 3.0); }
static inline double h_cpy(int k) { return -1.0 + (double)(k & 3) * (2.0 / 3.0); }

static void build_invw(InvW* out) {
    double M[NDIM][2 * NDIM];
    for (int r = 0; r < NDIM; r++)
        for (int c = 0; c < 2 * NDIM; c++) {
            double v = 0.0;
            if (c >= NDIM) {
                v = (c - NDIM == r) ? 1.0 : 0.0;
            } else if (r < KCP && c < KCP) {
                double dx = h_cpx(r) - h_cpx(c);
                double dy = h_cpy(r) - h_cpy(c);
                double r2 = dx * dx + dy * dy;
                v = r2 * log(r2 + 1e-6);
            } else if (r < KCP) {
                v = (c == KCP) ? 1.0 : ((c == KCP + 1) ? h_cpx(r) : h_cpy(r));
            } else if (c < KCP) {
                v = (r == KCP) ? 1.0 : ((r == KCP + 1) ? h_cpx(c) : h_cpy(c));
            }
            M[r][c] = v;
        }

    for (int p = 0; p < NDIM; p++) {
        int best = p;
        double bm = fabs(M[p][p]);
        for (int r = p + 1; r < NDIM; r++) {
            double m = fabs(M[r][p]);
            if (m > bm) { bm = m; best = r; }
        }
        if (best != p)
            for (int c = 0; c < 2 * NDIM; c++) {
                double tv = M[p][c]; M[p][c] = M[best][c]; M[best][c] = tv;
            }
        const double inv = 1.0 / M[p][p];
        for (int c = 0; c < 2 * NDIM; c++) M[p][c] *= inv;
        for (int r = 0; r < NDIM; r++) {
            if (r == p) continue;
            const double f = M[r][p];
            if (f == 0.0) continue;
            for (int c = 0; c < 2 * NDIM; c++) M[r][c] -= f * M[p][c];
        }
    }

    for (int i = 0; i < NDIM; i++)
        for (int j = 0; j < KCP; j++)
            out->w[i][j] = (float)M[i][NDIM + j];
}

// ---------------------------------------------------------------------------
extern "C" void kernel_launch(void* const* d_in, const int* in_sizes, int n_in,
                              void* d_out, int out_size) {
    const float* sp = (const float*)d_in[0];        // [64, 16, 2] fp32
    ulonglong2* out = (ulonglong2*)d_out;           // [64, 512, 512, 2] fp32

    InvW inv;
    build_invw(&inv);                               // host-side, capture-time only

    tps_fused_kernel<<<PAIRS / 256, 256>>>(inv, sp, out);
}

// round 10
// speedup vs baseline: 1.4297x; 1.0537x over previous
#include <cuda_runtime.h>
#include <cstdint>
#include <cmath>

#define B_SZ   64
#define KCP    16
#define NDIM   19            // K + 3
#define NPAD   20            // padded coeff rows per batch (16B alignment)
#define HH     512
#define WW     512
#define HWPIX  (HH * WW)
#define PAIRS  (HWPIX / 2)   // 131072 pixel pairs, 1 per thread

// inv_delta[:, :16] passed by value (computed on host — input-independent).
struct InvW {
    float w[NDIM][KCP];
};

// ---------------------------------------------------------------------------
// Packed f32x2 helpers (sm_103a).
// ---------------------------------------------------------------------------
__device__ __forceinline__ unsigned long long pack2(float lo, float hi) {
    unsigned long long r;
    asm("mov.b64 %0, {%1, %2};" : "=l"(r) : "f"(lo), "f"(hi));
    return r;
}
__device__ __forceinline__ unsigned long long fma2(unsigned long long a,
                                                   unsigned long long b,
                                                   unsigned long long c) {
    unsigned long long d;
    asm("fma.rn.f32x2 %0, %1, %2, %3;" : "=l"(d) : "l"(a), "l"(b), "l"(c));
    return d;
}
__device__ __forceinline__ unsigned long long add2(unsigned long long a,
                                                   unsigned long long b) {
    unsigned long long d;
    asm("add.rn.f32x2 %0, %1, %2;" : "=l"(d) : "l"(a), "l"(b));
    return d;
}

// ---------------------------------------------------------------------------
// Fused kernel: cheap prologue (warp-uniform weights via broadcast LDS,
// sp straight from L2) + R5's roofline-proven main loop.
// ---------------------------------------------------------------------------
__global__ void __launch_bounds__(256, 4) tps_fused_kernel(
    InvW inv, const float* __restrict__ sp, ulonglong2* __restrict__ out) {

    __shared__ __align__(16) float2 s_coeff[B_SZ * NPAD];  // 10 KB
    __shared__ __align__(16) float s_w[NDIM][KCP];         // 1.2 KB

    const int tid = threadIdx.x;

    // Stage invW into shared (304 floats = 76 float4; one-shot).
    {
        const float4* wsrc = reinterpret_cast<const float4*>(&inv.w[0][0]);
        float4* wdst = reinterpret_cast<float4*>(&s_w[0][0]);
        if (tid < (NDIM * KCP) / 4) wdst[tid] = wsrc[tid];
    }
    __syncthreads();

    // Coeff prologue: thread t -> batch b = t&63, row-group q = t>>6 (warp-
    // uniform). Rows i = q + 4m, m = 0..4 (q=3,m=4 -> pad row 19).
    {
        const int b = tid & 63;
        const int q = tid >> 6;
        const float2* spb = reinterpret_cast<const float2*>(sp) + b * KCP;
        float accx[5] = {0.f, 0.f, 0.f, 0.f, 0.f};
        float accy[5] = {0.f, 0.f, 0.f, 0.f, 0.f};
        #pragma unroll
        for (int j = 0; j < KCP; j++) {
            const float2 s = spb[j];                 // LDG.64 (L2-resident)
            #pragma unroll
            for (int m = 0; m < 5; m++) {
                const int i = q + 4 * m;
                if (i < NDIM) {
                    const float w = s_w[i][j];       // broadcast LDS
                    accx[m] = fmaf(w, s.x, accx[m]);
                    accy[m] = fmaf(w, s.y, accy[m]);
                }
            }
        }
        #pragma unroll
        for (int m = 0; m < 5; m++) {
            const int i = q + 4 * m;
            s_coeff[b * NPAD + i] =
                (i < NDIM) ? make_float2(accx[m], accy[m]) : make_float2(0.f, 0.f);
        }
    }
    __syncthreads();

    // ---- per-thread pixel pair (R5 main loop, at f32x2-issue roofline) ----
    const int t  = blockIdx.x * 256 + tid;
    const int n0 = t * 2;
    const int w0 = n0 & (WW - 1);
    const int h  = n0 >> 9;
    const float X0 = fmaf((float)w0, 2.0f / (float)(WW - 1), -1.0f);
    const float X1 = X0 + 2.0f / (float)(WW - 1);
    const float Y  = fmaf((float)h, 2.0f / (float)(HH - 1), -1.0f);

    unsigned long long u0[KCP], u1[KCP];
    #pragma unroll
    for (int k = 0; k < KCP; k++) {
        const float cx = -1.0f + (float)(k >> 2) * (2.0f / 3.0f);
        const float cy = -1.0f + (float)(k & 3) * (2.0f / 3.0f);
        const float dy  = Y - cy;
        const float dy2 = dy * dy;
        {
            float dx = X0 - cx;
            float r2 = fmaf(dx, dx, dy2);
            float u  = r2 * __logf(r2 + 1e-6f);
            u0[k] = pack2(u, u);
        }
        {
            float dx = X1 - cx;
            float r2 = fmaf(dx, dx, dy2);
            float u  = r2 * __logf(r2 + 1e-6f);
            u1[k] = pack2(u, u);
        }
    }
    const unsigned long long X0d = pack2(X0, X0);
    const unsigned long long X1d = pack2(X1, X1);
    const unsigned long long Yd  = pack2(Y, Y);

    #pragma unroll 4
    for (int b = 0; b < B_SZ; b++) {
        const ulonglong2* cc = reinterpret_cast<const ulonglong2*>(s_coeff + b * NPAD);
        // Affine part: rows 16 (const), 17 (x), 18 (y)
        const ulonglong2 c8 = cc[8];   // rows 16, 17
        const ulonglong2 c9 = cc[9];   // rows 18, pad
        unsigned long long a0 = fma2(X0d, c8.y, c8.x);
        unsigned long long a1 = fma2(X1d, c8.y, c8.x);
        a0 = fma2(Yd, c9.x, a0);
        a1 = fma2(Yd, c9.x, a1);
        unsigned long long b0 = 0ULL, b1 = 0ULL;
        #pragma unroll
        for (int j = 0; j < 8; j++) {
            const ulonglong2 c = cc[j];           // rows 2j, 2j+1 (broadcast LDS.128)
            a0 = fma2(u0[2 * j + 0], c.x, a0);
            b0 = fma2(u0[2 * j + 1], c.y, b0);
            a1 = fma2(u1[2 * j + 0], c.x, a1);
            b1 = fma2(u1[2 * j + 1], c.y, b1);
        }
        ulonglong2 r;
        r.x = add2(a0, b0);
        r.y = add2(a1, b1);
        out[(size_t)b * PAIRS + t] = r;           // STG.128
    }
}

// ---------------------------------------------------------------------------
// Host: build delta(19x19), invert (Gauss-Jordan, partial pivoting, fp64).
// Input-independent -> runs on CPU at capture time; rides in as kernel param.
// ---------------------------------------------------------------------------
static inline double h_cpx(int k) { return -1.0 + (double)(k >> 2) * (2.0 / 3.0); }
static inline double h_cpy(int k) { return -1.0 + (double)(k & 3) * (2.0 / 3.0); }

static void build_invw(InvW* out) {
    double M[NDIM][2 * NDIM];
    for (int r = 0; r < NDIM; r++)
        for (int c = 0; c < 2 * NDIM; c++) {
            double v = 0.0;
            if (c >= NDIM) {
                v = (c - NDIM == r) ? 1.0 : 0.0;
            } else if (r < KCP && c < KCP) {
                double dx = h_cpx(r) - h_cpx(c);
                double dy = h_cpy(r) - h_cpy(c);
                double r2 = dx * dx + dy * dy;
                v = r2 * log(r2 + 1e-6);
            } else if (r < KCP) {
                v = (c == KCP) ? 1.0 : ((c == KCP + 1) ? h_cpx(r) : h_cpy(r));
            } else if (c < KCP) {
                v = (r == KCP) ? 1.0 : ((r == KCP + 1) ? h_cpx(c) : h_cpy(c));
            }
            M[r][c] = v;
        }

    for (int p = 0; p < NDIM; p++) {
        int best = p;
        double bm = fabs(M[p][p]);
        for (int r = p + 1; r < NDIM; r++) {
            double m = fabs(M[r][p]);
            if (m > bm) { bm = m; best = r; }
        }
        if (best != p)
            for (int c = 0; c < 2 * NDIM; c++) {
                double tv = M[p][c]; M[p][c] = M[best][c]; M[best][c] = tv;
            }
        const double inv = 1.0 / M[p][p];
        for (int c = 0; c < 2 * NDIM; c++) M[p][c] *= inv;
        for (int r = 0; r < NDIM; r++) {
            if (r == p) continue;
            const double f = M[r][p];
            if (f == 0.0) continue;
            for (int c = 0; c < 2 * NDIM; c++) M[r][c] -= f * M[p][c];
        }
    }

    for (int i = 0; i < NDIM; i++)
        for (int j = 0; j < KCP; j++)
            out->w[i][j] = (float)M[i][NDIM + j];
}

// ---------------------------------------------------------------------------
extern "C" void kernel_launch(void* const* d_in, const int* in_sizes, int n_in,
                              void* d_out, int out_size) {
    const float* sp = (const float*)d_in[0];        // [64, 16, 2] fp32
    ulonglong2* out = (ulonglong2*)d_out;           // [64, 512, 512, 2] fp32

    InvW inv;
    build_invw(&inv);                               // host-side, capture-time only

    tps_fused_kernel<<<PAIRS / 256, 256>>>(inv, sp, out);
}